// round 13
// baseline (speedup 1.0000x reference)
#include <cuda_runtime.h>
#include <cuda_fp16.h>
#include <cstdint>
#include <math.h>

// GRU-style decoder cell via mma.sync fp16 (m16n8k16, fp32 accum).
// r,z fused into one N=2048 GEMM; x,c read as fp32 with in-loop conversion.
//   r = sigmoid(x@Wr^T + hprev@Ur^T + c@Cr^T + br)   -> g_rh2 = fp16(r*hprev)
//   z = sigmoid(x@Wz^T + hprev@Uz^T + c@Cz^T + bz)   -> g_z (fp32)
//   h = tanh   (x@Wh^T + g_rh2@Uh^T + c@Ch^T + bh)   -> out = z*h + (1-z)*hprev
// B=8192, IN=1024, H=1024, c:[B,2048]; effective K=4096 per gate.

#define BATCH 8192
#define HID   1024
#define BM 128
#define BN 128
#define BK 32
#define STAGES 4
#define NCHUNK 128

#define A_SLOT 4096                 // floats per A stage (16 KB; fp16 seg uses half)
#define B_SLOT 4096                 // halves per B stage (8 KB)
#define SMEM_BYTES (STAGES * (A_SLOT * 4 + B_SLOT * 2))   // 98304 -> 2 CTAs/SM

// ---- scratch (allocation-free) ----
__device__ __half g_h2 [(size_t)BATCH * 1024];
__device__ __half g_rh2[(size_t)BATCH * HID];
__device__ float  g_z  [(size_t)BATCH * HID];
// rzW[2M] rzU[2M] rzC[4M] hW[1M] hU[1M] hC[2M]  (halves)
__device__ __half g_w2 [(size_t)12 * 1024 * 1024];

__device__ __forceinline__ void cp16(void* dst_smem, const void* src) {
    uint32_t d = (uint32_t)__cvta_generic_to_shared(dst_smem);
    asm volatile("cp.async.cg.shared.global [%0], [%1], 16;" :: "r"(d), "l"(src));
}
__device__ __forceinline__ void cp_commit() {
    asm volatile("cp.async.commit_group;" ::: "memory");
}
__device__ __forceinline__ void cp_wait2() {
    asm volatile("cp.async.wait_group 2;" ::: "memory");
}
__device__ __forceinline__ uint32_t h2_bits(__half2 h) {
    return *reinterpret_cast<uint32_t*>(&h);
}
__device__ __forceinline__ uint32_t packh2(float a, float b) {
    __half2 h = __floats2half2_rn(a, b);
    return *reinterpret_cast<uint32_t*>(&h);
}
__device__ __forceinline__ void mma_f16(float* c, uint32_t a0, uint32_t a1,
                                        uint32_t a2, uint32_t a3,
                                        uint32_t b0, uint32_t b1) {
    asm volatile(
        "mma.sync.aligned.m16n8k16.row.col.f32.f16.f16.f32 "
        "{%0,%1,%2,%3}, {%4,%5,%6,%7}, {%8,%9}, {%0,%1,%2,%3};"
        : "+f"(c[0]), "+f"(c[1]), "+f"(c[2]), "+f"(c[3])
        : "r"(a0), "r"(a1), "r"(a2), "r"(a3), "r"(b0), "r"(b1));
}
__device__ __forceinline__ float fsigmoid(float v) { return 1.0f / (1.0f + __expf(-v)); }
__device__ __forceinline__ float ftanh(float v) {
    float e = __expf(-2.0f * v);
    return 2.0f / (1.0f + e) - 1.0f;
}

// ---- consolidated fp32 -> fp16 conversion (hprev + weights only) ----
#define NSEG 10
struct CvtSegs {
    const float4* src[NSEG];
    uint2*        dst[NSEG];
    int           off[NSEG + 1];
};

__global__ __launch_bounds__(256)
void cvt_all_kernel(const __grid_constant__ CvtSegs segs)
{
    const int total  = segs.off[NSEG];
    const int stride = gridDim.x * blockDim.x;
    for (int i = blockIdx.x * blockDim.x + threadIdx.x; i < total; i += stride) {
        int s = 0;
#pragma unroll
        for (int k = 1; k < NSEG; ++k)
            if (i >= segs.off[k]) s = k;
        const int j = i - segs.off[s];
        const float4 v = segs.src[s][j];
        uint2 o;
        o.x = h2_bits(__floats2half2_rn(v.x, v.y));
        o.y = h2_bits(__floats2half2_rn(v.z, v.w));
        segs.dst[s][j] = o;
    }
}

// mode 0: fused rz (bn<1024 -> rh2 fp16; else -> z fp32)
// mode 2: final h   (out = z*tanh + (1-z)*hprev)
__global__ __launch_bounds__(256, 2)
void gate_mma_kernel(
    const float*  __restrict__ xf,    // fp32 [B,1024]  (seg0)
    const __half* __restrict__ A1,    // fp16 [B,1024]  (seg1: g_h2 or g_rh2)
    const float*  __restrict__ cf,    // fp32 [B,2048]  (seg2)
    const __half* __restrict__ W0,
    const __half* __restrict__ W1,
    const __half* __restrict__ W2,
    const float* __restrict__ bias_a,
    const float* __restrict__ bias_b,
    const float* __restrict__ hprev,
    const float* __restrict__ zbuf,
    __half* __restrict__ out_h,
    float* __restrict__ out_f,
    int mode)
{
    extern __shared__ float smf[];
    float*  As = smf;                              // STAGES x 4096 floats
    __half* Bs = (__half*)(smf + STAGES * A_SLOT); // STAGES x 4096 halves

    const int tid  = threadIdx.x;
    const int lane = tid & 31;
    const int wid  = tid >> 5;
    const int g    = lane >> 2;
    const int tg   = lane & 3;
    const int wm   = wid >> 2;
    const int wn   = wid & 3;

    const int bm = blockIdx.y * BM;
    const int bn = blockIdx.x * BN;

    // fp16 lane-constant swizzled offset (halves): frag rows have row&3 == g&3
    const int loff = ((tg ^ (g & 3)) << 3);
    // fp32 lane-constant swizzled chunk offsets (floats): frag rows have row&1 == g&1
    const int coff0 = (((2 * tg + 0) ^ (g & 1)) << 2);
    const int coff1 = (((2 * tg + 1) ^ (g & 1)) << 2);

    float acc[4][4][4];
#pragma unroll
    for (int i = 0; i < 4; ++i)
#pragma unroll
        for (int j = 0; j < 4; ++j)
#pragma unroll
            for (int k = 0; k < 4; ++k)
                acc[i][j][k] = 0.0f;

    auto issue = [&](int i) {
        const int s = i & 3;
        // ---- A segment ----
        if (i >= 32 && i < 64) {
            // fp16 A (hprev/rh2)
            const int k0 = (i - 32) * BK;
            __half* ad = (__half*)(As + s * A_SLOT);
#pragma unroll
            for (int j = 0; j < 2; ++j) {
                const int idx = tid + j * 256;
                const int row = idx >> 2;
                const int ch  = idx & 3;
                const int swc = ch ^ (row & 3);
                cp16(ad + row * 32 + (swc << 3),
                     A1 + (size_t)(bm + row) * 1024 + k0 + (ch << 3));
            }
        } else {
            // fp32 A (x or c)
            const float* Aseg;
            int ld, k0;
            if (i < 32) { Aseg = xf; ld = 1024; k0 = i * BK; }
            else        { Aseg = cf; ld = 2048; k0 = (i - 64) * BK; }
            float* ad = As + s * A_SLOT;
#pragma unroll
            for (int j = 0; j < 4; ++j) {
                const int idx = tid + j * 256;
                const int row = idx >> 3;
                const int ch  = idx & 7;
                const int swc = ch ^ (row & 1);
                cp16(ad + row * 32 + (swc << 2),
                     Aseg + (size_t)(bm + row) * ld + k0 + (ch << 2));
            }
        }
        // ---- B segment (always fp16) ----
        const __half* Wseg;
        int ld, k0;
        if (i < 32)      { Wseg = W0; ld = 1024; k0 = i * BK; }
        else if (i < 64) { Wseg = W1; ld = 1024; k0 = (i - 32) * BK; }
        else             { Wseg = W2; ld = 2048; k0 = (i - 64) * BK; }
        __half* bd = Bs + s * B_SLOT;
#pragma unroll
        for (int j = 0; j < 2; ++j) {
            const int idx = tid + j * 256;
            const int row = idx >> 2;
            const int ch  = idx & 3;
            const int swc = ch ^ (row & 3);
            cp16(bd + row * 32 + (swc << 3),
                 Wseg + (size_t)(bn + row) * ld + k0 + (ch << 3));
        }
        cp_commit();
    };

    issue(0); issue(1); issue(2);

    for (int i = 0; i < NCHUNK; ++i) {
        cp_wait2();
        __syncthreads();
        if (i + 3 < NCHUNK) issue(i + 3);

        const int buf = i & 3;
        const __half* B0 = Bs + buf * B_SLOT + (wn * 32) * 32;

        uint4 bv[4];
#pragma unroll
        for (int nf = 0; nf < 4; ++nf)
            bv[nf] = *(const uint4*)(B0 + (nf * 8 + g) * 32 + loff);

        if (i >= 32 && i < 64) {
            // fp16 A fragments
            const __half* A0 = (const __half*)(As + buf * A_SLOT) + (wm * 64) * 32;
#pragma unroll
            for (int mf = 0; mf < 4; ++mf) {
                const uint4 a0 = *(const uint4*)(A0 + (mf * 16 + g) * 32 + loff);
                const uint4 a1 = *(const uint4*)(A0 + (mf * 16 + g + 8) * 32 + loff);
#pragma unroll
                for (int nf = 0; nf < 4; ++nf)
                    mma_f16(acc[mf][nf], a0.x, a1.x, a0.y, a1.y, bv[nf].x, bv[nf].y);
#pragma unroll
                for (int nf = 0; nf < 4; ++nf)
                    mma_f16(acc[mf][nf], a0.z, a1.z, a0.w, a1.w, bv[nf].z, bv[nf].w);
            }
        } else {
            // fp32 A fragments, convert in-loop
            const float* A0 = As + buf * A_SLOT + (wm * 64) * 32;
#pragma unroll
            for (int mf = 0; mf < 4; ++mf) {
                const float* p0 = A0 + (mf * 16 + g) * 32;
                const float* p1 = A0 + (mf * 16 + g + 8) * 32;
                const float4 x0 = *(const float4*)(p0 + coff0);
                const float4 x1 = *(const float4*)(p0 + coff1);
                const float4 y0 = *(const float4*)(p1 + coff0);
                const float4 y1 = *(const float4*)(p1 + coff1);
                uint4 a0, a1;
                a0.x = packh2(x0.x, x0.y); a0.y = packh2(x0.z, x0.w);
                a0.z = packh2(x1.x, x1.y); a0.w = packh2(x1.z, x1.w);
                a1.x = packh2(y0.x, y0.y); a1.y = packh2(y0.z, y0.w);
                a1.z = packh2(y1.x, y1.y); a1.w = packh2(y1.z, y1.w);
#pragma unroll
                for (int nf = 0; nf < 4; ++nf)
                    mma_f16(acc[mf][nf], a0.x, a1.x, a0.y, a1.y, bv[nf].x, bv[nf].y);
#pragma unroll
                for (int nf = 0; nf < 4; ++nf)
                    mma_f16(acc[mf][nf], a0.z, a1.z, a0.w, a1.w, bv[nf].z, bv[nf].w);
            }
        }
    }

    // ---- epilogue ----
    const bool is_r = (bn < 1024);
    const float* bias = (mode == 2) ? bias_a : (is_r ? bias_a : bias_b - 1024);

#pragma unroll
    for (int mf = 0; mf < 4; ++mf) {
#pragma unroll
        for (int nf = 0; nf < 4; ++nf) {
            const int n = bn + wn * 32 + nf * 8 + 2 * tg;
            const float2 bi = *(const float2*)(bias + n);
#pragma unroll
            for (int half = 0; half < 2; ++half) {
                const int m = bm + wm * 64 + mf * 16 + g + half * 8;
                float v0 = acc[mf][nf][2 * half + 0] + bi.x;
                float v1 = acc[mf][nf][2 * half + 1] + bi.y;
                if (mode == 0) {
                    if (is_r) {
                        const size_t idx = (size_t)m * HID + n;
                        const float2 hp = *(const float2*)(hprev + idx);
                        *(__half2*)(out_h + idx) =
                            __floats2half2_rn(fsigmoid(v0) * hp.x, fsigmoid(v1) * hp.y);
                    } else {
                        const size_t idx = (size_t)m * HID + (n - 1024);
                        float2 o;
                        o.x = fsigmoid(v0);
                        o.y = fsigmoid(v1);
                        *(float2*)(out_f + idx) = o;
                    }
                } else {
                    const size_t idx = (size_t)m * HID + n;
                    const float2 hp = *(const float2*)(hprev + idx);
                    const float2 zz = *(const float2*)(zbuf + idx);
                    float2 o;
                    o.x = fmaf(zz.x, ftanh(v0) - hp.x, hp.x);
                    o.y = fmaf(zz.y, ftanh(v1) - hp.y, hp.y);
                    *(float2*)(out_f + idx) = o;
                }
            }
        }
    }
}

extern "C" void kernel_launch(void* const* d_in, const int* in_sizes, int n_in,
                              void* d_out, int out_size)
{
    const float* x     = (const float*)d_in[0];
    const float* hprev = (const float*)d_in[1];
    const float* c     = (const float*)d_in[2];
    const float* Wh    = (const float*)d_in[3];
    const float* Wz    = (const float*)d_in[4];
    const float* Wr    = (const float*)d_in[5];
    const float* Uh    = (const float*)d_in[6];
    const float* Uz    = (const float*)d_in[7];
    const float* Ur    = (const float*)d_in[8];
    const float* Ch    = (const float*)d_in[9];
    const float* Cz    = (const float*)d_in[10];
    const float* Cr    = (const float*)d_in[11];
    const float* bh    = (const float*)d_in[12];
    const float* bz    = (const float*)d_in[13];
    const float* br    = (const float*)d_in[14];
    float* out = (float*)d_out;

    __half *h2, *rh2, *w2;
    float *z_p;
    cudaGetSymbolAddress((void**)&h2,  g_h2);
    cudaGetSymbolAddress((void**)&rh2, g_rh2);
    cudaGetSymbolAddress((void**)&z_p, g_z);
    cudaGetSymbolAddress((void**)&w2,  g_w2);

    const size_t M1 = (size_t)1024 * 1024;
    __half* rzW = w2;                 // [2048,1024]
    __half* rzU = w2 + 2 * M1;        // [2048,1024]
    __half* rzC = w2 + 4 * M1;        // [2048,2048]
    __half* hW  = w2 + 8 * M1;        // [1024,1024]
    __half* hU  = w2 + 9 * M1;
    __half* hC  = w2 + 10 * M1;       // [1024,2048]

    // ---- one conversion launch: hprev + weights only ----
    CvtSegs segs;
    const float* srcs[NSEG] = { hprev,
                                Wr, Wz, Ur, Uz, Cr, Cz,
                                Wh, Uh, Ch };
    __half* dsts[NSEG] = { h2,
                           rzW, rzW + M1, rzU, rzU + M1, rzC, rzC + 2 * M1,
                           hW, hU, hC };
    const size_t cnts[NSEG] = { (size_t)BATCH * 1024,
                                M1, M1, M1, M1, 2 * M1, 2 * M1,
                                M1, M1, 2 * M1 };
    int off = 0;
    for (int s = 0; s < NSEG; ++s) {
        segs.src[s] = (const float4*)srcs[s];
        segs.dst[s] = (uint2*)dsts[s];
        segs.off[s] = off;
        off += (int)(cnts[s] / 4);
    }
    segs.off[NSEG] = off;
    cvt_all_kernel<<<2960, 256>>>(segs);

    cudaFuncSetAttribute(gate_mma_kernel,
                         cudaFuncAttributeMaxDynamicSharedMemorySize, SMEM_BYTES);

    const dim3 block(256);

    // fused r+z: N = 2048
    gate_mma_kernel<<<dim3(2048 / BN, BATCH / BM), block, SMEM_BYTES>>>(
        x, h2, c, rzW, rzU, rzC, br, bz, hprev, nullptr, rh2, z_p, 0);
    // h gate: N = 1024
    gate_mma_kernel<<<dim3(HID / BN, BATCH / BM), block, SMEM_BYTES>>>(
        x, rh2, c, hW, hU, hC, bh, nullptr, hprev, z_p, nullptr, out, 2);
}

// round 14
// speedup vs baseline: 1.1776x; 1.1776x over previous
#include <cuda_runtime.h>
#include <cuda_fp16.h>
#include <cstdint>
#include <math.h>

// GRU-style decoder cell via mma.sync fp16 (m16n8k16, fp32 accum).
// r,z fused into one N=2048 GEMM (stacked weights); h gate uses 128x64 tiles
// at 4 CTAs/SM to kill wave quantization.
//   r = sigmoid(x@Wr^T + hprev@Ur^T + c@Cr^T + br)   -> g_rh2 = fp16(r*hprev)
//   z = sigmoid(x@Wz^T + hprev@Uz^T + c@Cz^T + bz)   -> g_z (fp32)
//   h = tanh   (x@Wh^T + g_rh2@Uh^T + c@Ch^T + bh)   -> out = z*h + (1-z)*hprev
// B=8192, IN=1024, H=1024, c:[B,2048]; effective K=4096 per gate.

#define BATCH 8192
#define HID   1024
#define BM 128
#define BK 32            // halves per chunk
#define STAGES 4
#define NCHUNK 128       // 4096 / 32

#define A_TILE (BM * BK) // 4096 halves

// ---- scratch (allocation-free) ----
__device__ __half g_x2 [(size_t)BATCH * 1024];
__device__ __half g_h2 [(size_t)BATCH * 1024];
__device__ __half g_c2 [(size_t)BATCH * 2048];
__device__ __half g_rh2[(size_t)BATCH * HID];
__device__ float  g_z  [(size_t)BATCH * HID];
// rzW[2M] rzU[2M] rzC[4M] hW[1M] hU[1M] hC[2M]  (halves)
__device__ __half g_w2 [(size_t)12 * 1024 * 1024];

__device__ __forceinline__ void cp16(void* dst_smem, const void* src) {
    uint32_t d = (uint32_t)__cvta_generic_to_shared(dst_smem);
    asm volatile("cp.async.cg.shared.global [%0], [%1], 16;" :: "r"(d), "l"(src));
}
__device__ __forceinline__ void cp_commit() {
    asm volatile("cp.async.commit_group;" ::: "memory");
}
__device__ __forceinline__ void cp_wait2() {
    asm volatile("cp.async.wait_group 2;" ::: "memory");
}
__device__ __forceinline__ uint32_t h2_bits(__half2 h) {
    return *reinterpret_cast<uint32_t*>(&h);
}
__device__ __forceinline__ void mma_f16(float* c, uint32_t a0, uint32_t a1,
                                        uint32_t a2, uint32_t a3,
                                        uint32_t b0, uint32_t b1) {
    asm volatile(
        "mma.sync.aligned.m16n8k16.row.col.f32.f16.f16.f32 "
        "{%0,%1,%2,%3}, {%4,%5,%6,%7}, {%8,%9}, {%0,%1,%2,%3};"
        : "+f"(c[0]), "+f"(c[1]), "+f"(c[2]), "+f"(c[3])
        : "r"(a0), "r"(a1), "r"(a2), "r"(a3), "r"(b0), "r"(b1));
}
__device__ __forceinline__ float fsigmoid(float v) { return 1.0f / (1.0f + __expf(-v)); }
__device__ __forceinline__ float ftanh(float v) {
    float e = __expf(-2.0f * v);
    return 2.0f / (1.0f + e) - 1.0f;
}

// ---- consolidated fp32 -> fp16 conversion over 12 segments ----
#define NSEG 12
struct CvtSegs {
    const float4* src[NSEG];
    uint2*        dst[NSEG];
    int           off[NSEG + 1];
};

__global__ __launch_bounds__(256)
void cvt_all_kernel(const __grid_constant__ CvtSegs segs)
{
    const int total  = segs.off[NSEG];
    const int stride = gridDim.x * blockDim.x;
    for (int i = blockIdx.x * blockDim.x + threadIdx.x; i < total; i += stride) {
        int s = 0;
#pragma unroll
        for (int k = 1; k < NSEG; ++k)
            if (i >= segs.off[k]) s = k;
        const int j = i - segs.off[s];
        const float4 v = segs.src[s][j];
        uint2 o;
        o.x = h2_bits(__floats2half2_rn(v.x, v.y));
        o.y = h2_bits(__floats2half2_rn(v.z, v.w));
        segs.dst[s][j] = o;
    }
}

// mode 0: fused rz (bn<1024 -> rh2 fp16; else -> z fp32)
// mode 2: final h   (out = z*tanh + (1-z)*hprev)
template <int BN_, int THREADS, int MAXCTA>
__global__ __launch_bounds__(THREADS, MAXCTA)
void gate_mma_kernel(
    const __half* __restrict__ x,
    const __half* __restrict__ A1,
    const __half* __restrict__ c,
    const __half* __restrict__ W0,
    const __half* __restrict__ W1,
    const __half* __restrict__ W2,
    const float* __restrict__ bias_a,
    const float* __restrict__ bias_b,
    const float* __restrict__ hprev,
    const float* __restrict__ zbuf,
    __half* __restrict__ out_h,
    float* __restrict__ out_f,
    int mode)
{
    constexpr int B_TILE = BN_ * BK;
    constexpr int BNW = BN_ / 32;   // N-slabs of 32 cols

    extern __shared__ __half sh[];
    __half* As = sh;
    __half* Bs = sh + STAGES * A_TILE;

    const int tid  = threadIdx.x;
    const int lane = tid & 31;
    const int wid  = tid >> 5;
    const int g    = lane >> 2;
    const int tg   = lane & 3;
    const int wm   = wid / BNW;      // 0..1 -> 64-row slab
    const int wn   = wid % BNW;      // 32-col slab

    const int bm = blockIdx.y * BM;
    const int bn = blockIdx.x * BN_;

    const int loff = ((tg ^ (g & 3)) << 3);

    float acc[4][4][4];
#pragma unroll
    for (int i = 0; i < 4; ++i)
#pragma unroll
        for (int j = 0; j < 4; ++j)
#pragma unroll
            for (int k = 0; k < 4; ++k)
                acc[i][j][k] = 0.0f;

    auto issue = [&](int i) {
        const int s = i & 3;
        const __half* Aseg;
        const __half* Wseg;
        int ld, k0;
        if (i < 32)      { Aseg = x;  Wseg = W0; ld = 1024; k0 = i * BK; }
        else if (i < 64) { Aseg = A1; Wseg = W1; ld = 1024; k0 = (i - 32) * BK; }
        else             { Aseg = c;  Wseg = W2; ld = 2048; k0 = (i - 64) * BK; }

        __half* ad = As + s * A_TILE;
        __half* bd = Bs + s * B_TILE;
        // A: 128 rows x 4 chunks(16B) = 512 cp16
#pragma unroll
        for (int j = 0; j < 512 / THREADS; ++j) {
            const int idx = tid + j * THREADS;
            const int row = idx >> 2;
            const int ch  = idx & 3;
            const int swc = ch ^ (row & 3);
            cp16(ad + row * 32 + (swc << 3),
                 Aseg + (size_t)(bm + row) * ld + k0 + (ch << 3));
        }
        // B: BN_ rows x 4 chunks
#pragma unroll
        for (int j = 0; j < (BN_ * 4) / THREADS; ++j) {
            const int idx = tid + j * THREADS;
            const int row = idx >> 2;
            const int ch  = idx & 3;
            const int swc = ch ^ (row & 3);
            cp16(bd + row * 32 + (swc << 3),
                 Wseg + (size_t)(bn + row) * ld + k0 + (ch << 3));
        }
        cp_commit();
    };

    issue(0); issue(1); issue(2);

    for (int i = 0; i < NCHUNK; ++i) {
        cp_wait2();
        __syncthreads();
        if (i + 3 < NCHUNK) issue(i + 3);

        const int buf = i & 3;
        const __half* A0 = As + buf * A_TILE + (wm * 64) * 32;
        const __half* B0 = Bs + buf * B_TILE + (wn * 32) * 32;

        uint4 bv[4];
#pragma unroll
        for (int nf = 0; nf < 4; ++nf)
            bv[nf] = *(const uint4*)(B0 + (nf * 8 + g) * 32 + loff);

#pragma unroll
        for (int mf = 0; mf < 4; ++mf) {
            const uint4 a0 = *(const uint4*)(A0 + (mf * 16 + g) * 32 + loff);
            const uint4 a1 = *(const uint4*)(A0 + (mf * 16 + g + 8) * 32 + loff);
#pragma unroll
            for (int nf = 0; nf < 4; ++nf)
                mma_f16(acc[mf][nf], a0.x, a1.x, a0.y, a1.y, bv[nf].x, bv[nf].y);
#pragma unroll
            for (int nf = 0; nf < 4; ++nf)
                mma_f16(acc[mf][nf], a0.z, a1.z, a0.w, a1.w, bv[nf].z, bv[nf].w);
        }
    }

    // ---- epilogue ----
    const bool is_r = (bn < 1024);
    const float* bias = (mode == 2) ? bias_a : (is_r ? bias_a : bias_b - 1024);

#pragma unroll
    for (int mf = 0; mf < 4; ++mf) {
#pragma unroll
        for (int nf = 0; nf < 4; ++nf) {
            const int n = bn + wn * 32 + nf * 8 + 2 * tg;
            const float2 bi = *(const float2*)(bias + n);
#pragma unroll
            for (int half = 0; half < 2; ++half) {
                const int m = bm + wm * 64 + mf * 16 + g + half * 8;
                float v0 = acc[mf][nf][2 * half + 0] + bi.x;
                float v1 = acc[mf][nf][2 * half + 1] + bi.y;
                if (mode == 0) {
                    if (is_r) {
                        const size_t idx = (size_t)m * HID + n;
                        const float2 hp = *(const float2*)(hprev + idx);
                        *(__half2*)(out_h + idx) =
                            __floats2half2_rn(fsigmoid(v0) * hp.x, fsigmoid(v1) * hp.y);
                    } else {
                        const size_t idx = (size_t)m * HID + (n - 1024);
                        float2 o;
                        o.x = fsigmoid(v0);
                        o.y = fsigmoid(v1);
                        *(float2*)(out_f + idx) = o;
                    }
                } else {
                    const size_t idx = (size_t)m * HID + n;
                    const float2 hp = *(const float2*)(hprev + idx);
                    const float2 zz = *(const float2*)(zbuf + idx);
                    float2 o;
                    o.x = fmaf(zz.x, ftanh(v0) - hp.x, hp.x);
                    o.y = fmaf(zz.y, ftanh(v1) - hp.y, hp.y);
                    *(float2*)(out_f + idx) = o;
                }
            }
        }
    }
}

extern "C" void kernel_launch(void* const* d_in, const int* in_sizes, int n_in,
                              void* d_out, int out_size)
{
    const float* x     = (const float*)d_in[0];
    const float* hprev = (const float*)d_in[1];
    const float* c     = (const float*)d_in[2];
    const float* Wh    = (const float*)d_in[3];
    const float* Wz    = (const float*)d_in[4];
    const float* Wr    = (const float*)d_in[5];
    const float* Uh    = (const float*)d_in[6];
    const float* Uz    = (const float*)d_in[7];
    const float* Ur    = (const float*)d_in[8];
    const float* Ch    = (const float*)d_in[9];
    const float* Cz    = (const float*)d_in[10];
    const float* Cr    = (const float*)d_in[11];
    const float* bh    = (const float*)d_in[12];
    const float* bz    = (const float*)d_in[13];
    const float* br    = (const float*)d_in[14];
    float* out = (float*)d_out;

    __half *x2, *h2, *c2, *rh2, *w2;
    float *z_p;
    cudaGetSymbolAddress((void**)&x2,  g_x2);
    cudaGetSymbolAddress((void**)&h2,  g_h2);
    cudaGetSymbolAddress((void**)&c2,  g_c2);
    cudaGetSymbolAddress((void**)&rh2, g_rh2);
    cudaGetSymbolAddress((void**)&z_p, g_z);
    cudaGetSymbolAddress((void**)&w2,  g_w2);

    const size_t M1 = (size_t)1024 * 1024;
    __half* rzW = w2;                 // [2048,1024]
    __half* rzU = w2 + 2 * M1;        // [2048,1024]
    __half* rzC = w2 + 4 * M1;        // [2048,2048]
    __half* hW  = w2 + 8 * M1;        // [1024,1024]
    __half* hU  = w2 + 9 * M1;
    __half* hC  = w2 + 10 * M1;       // [1024,2048]

    // ---- one conversion launch, 12 segments ----
    CvtSegs segs;
    const float* srcs[NSEG] = { x, hprev, c,
                                Wr, Wz, Ur, Uz, Cr, Cz,
                                Wh, Uh, Ch };
    __half* dsts[NSEG] = { x2, h2, c2,
                           rzW, rzW + M1, rzU, rzU + M1, rzC, rzC + 2 * M1,
                           hW, hU, hC };
    const size_t cnts[NSEG] = { (size_t)BATCH * 1024, (size_t)BATCH * 1024, (size_t)BATCH * 2048,
                                M1, M1, M1, M1, 2 * M1, 2 * M1,
                                M1, M1, 2 * M1 };
    int off = 0;
    for (int s = 0; s < NSEG; ++s) {
        segs.src[s] = (const float4*)srcs[s];
        segs.dst[s] = (uint2*)dsts[s];
        segs.off[s] = off;
        off += (int)(cnts[s] / 4);
    }
    segs.off[NSEG] = off;
    cvt_all_kernel<<<2960, 256>>>(segs);

    // rz kernel: BN=128, 256 threads, 2 CTAs/SM
    constexpr int SMEM_RZ = STAGES * (A_TILE + 128 * BK) * 2;   // 65536
    // h kernel: BN=64, 128 threads, 4 CTAs/SM
    constexpr int SMEM_H  = STAGES * (A_TILE + 64 * BK) * 2;    // 49152

    cudaFuncSetAttribute((const void*)gate_mma_kernel<128, 256, 2>,
                         cudaFuncAttributeMaxDynamicSharedMemorySize, SMEM_RZ);
    cudaFuncSetAttribute((const void*)gate_mma_kernel<64, 128, 4>,
                         cudaFuncAttributeMaxDynamicSharedMemorySize, SMEM_H);

    // fused r+z: N = 2048, grid (16, 64) = 1024 CTAs
    gate_mma_kernel<128, 256, 2><<<dim3(2048 / 128, BATCH / BM), 256, SMEM_RZ>>>(
        x2, h2, c2, rzW, rzU, rzC, br, bz, hprev, nullptr, rh2, z_p, 0);
    // h gate: N = 1024, BN=64 -> grid (16, 64) = 1024 CTAs, 4/SM
    gate_mma_kernel<64, 128, 4><<<dim3(1024 / 64, BATCH / BM), 128, SMEM_H>>>(
        x2, rh2, c2, hW, hU, hC, bh, nullptr, hprev, z_p, nullptr, out, 2);
}

// round 16
// speedup vs baseline: 1.2059x; 1.0240x over previous
#include <cuda_runtime.h>
#include <cuda_fp16.h>
#include <cstdint>
#include <math.h>

// GRU-style decoder cell via mma.sync fp16 (m16n8k16, fp32 accum).
// rz fused (N=2048), 6-stage pipeline w/ 2 chunks per barrier;
// h gate 128x64 tiles at 4 CTAs/SM (4 stages, 1 chunk/barrier).
//   r = sigmoid(x@Wr^T + hprev@Ur^T + c@Cr^T + br)   -> g_rh2 = fp16(r*hprev)
//   z = sigmoid(x@Wz^T + hprev@Uz^T + c@Cz^T + bz)   -> g_z (fp32)
//   h = tanh   (x@Wh^T + g_rh2@Uh^T + c@Ch^T + bh)   -> out = z*h + (1-z)*hprev

#define BATCH 8192
#define HID   1024
#define BM 128
#define BK 32            // halves per chunk
#define NCHUNK 128       // 4096 / 32

#define A_TILE (BM * BK) // 4096 halves

// ---- scratch (allocation-free) ----
__device__ __half g_x2 [(size_t)BATCH * 1024];
__device__ __half g_h2 [(size_t)BATCH * 1024];
__device__ __half g_c2 [(size_t)BATCH * 2048];
__device__ __half g_rh2[(size_t)BATCH * HID];
__device__ float  g_z  [(size_t)BATCH * HID];
__device__ __half g_w2 [(size_t)12 * 1024 * 1024];

__device__ __forceinline__ void cp16(void* dst_smem, const void* src) {
    uint32_t d = (uint32_t)__cvta_generic_to_shared(dst_smem);
    asm volatile("cp.async.cg.shared.global [%0], [%1], 16;" :: "r"(d), "l"(src));
}
__device__ __forceinline__ void cp_commit() {
    asm volatile("cp.async.commit_group;" ::: "memory");
}
__device__ __forceinline__ void cp_wait2() {
    asm volatile("cp.async.wait_group 2;" ::: "memory");
}
__device__ __forceinline__ uint32_t h2_bits(__half2 h) {
    return *reinterpret_cast<uint32_t*>(&h);
}
__device__ __forceinline__ void mma_f16(float* c, uint32_t a0, uint32_t a1,
                                        uint32_t a2, uint32_t a3,
                                        uint32_t b0, uint32_t b1) {
    asm volatile(
        "mma.sync.aligned.m16n8k16.row.col.f32.f16.f16.f32 "
        "{%0,%1,%2,%3}, {%4,%5,%6,%7}, {%8,%9}, {%0,%1,%2,%3};"
        : "+f"(c[0]), "+f"(c[1]), "+f"(c[2]), "+f"(c[3])
        : "r"(a0), "r"(a1), "r"(a2), "r"(a3), "r"(b0), "r"(b1));
}
__device__ __forceinline__ float fsigmoid(float v) { return 1.0f / (1.0f + __expf(-v)); }
__device__ __forceinline__ float ftanh(float v) {
    float e = __expf(-2.0f * v);
    return 2.0f / (1.0f + e) - 1.0f;
}

// ---- consolidated fp32 -> fp16 conversion over 12 segments ----
#define NSEG 12
struct CvtSegs {
    const float4* src[NSEG];
    uint2*        dst[NSEG];
    int           off[NSEG + 1];
};

__global__ __launch_bounds__(256)
void cvt_all_kernel(const __grid_constant__ CvtSegs segs)
{
    const int total  = segs.off[NSEG];
    const int stride = gridDim.x * blockDim.x;
    for (int i = blockIdx.x * blockDim.x + threadIdx.x; i < total; i += stride) {
        int s = 0;
#pragma unroll
        for (int k = 1; k < NSEG; ++k)
            if (i >= segs.off[k]) s = k;
        const int j = i - segs.off[s];
        const float4 v = segs.src[s][j];
        uint2 o;
        o.x = h2_bits(__floats2half2_rn(v.x, v.y));
        o.y = h2_bits(__floats2half2_rn(v.z, v.w));
        segs.dst[s][j] = o;
    }
}

// mode 0: fused rz (bn<1024 -> rh2 fp16; else -> z fp32)
// mode 2: final h   (out = z*tanh + (1-z)*hprev)
// Pipeline invariant: prefill = NSTAGES - BATCH_CH groups; cp_wait2 leaves <=2
// groups pending, so (prefill - 2) == BATCH_CH chunks are guaranteed complete.
template <int BN_, int THREADS, int MAXCTA, int NSTAGES, int BATCH_CH>
__global__ __launch_bounds__(THREADS, MAXCTA)
void gate_mma_kernel(
    const __half* __restrict__ x,
    const __half* __restrict__ A1,
    const __half* __restrict__ c,
    const __half* __restrict__ W0,
    const __half* __restrict__ W1,
    const __half* __restrict__ W2,
    const float* __restrict__ bias_a,
    const float* __restrict__ bias_b,
    const float* __restrict__ hprev,
    const float* __restrict__ zbuf,
    __half* __restrict__ out_h,
    float* __restrict__ out_f,
    int mode)
{
    constexpr int B_TILE = BN_ * BK;
    constexpr int BNW = BN_ / 32;
    constexpr int PREFILL = NSTAGES - BATCH_CH;
    static_assert(PREFILL - 2 == BATCH_CH, "wait_group 2 must guarantee BATCH_CH chunks");

    extern __shared__ __half sh[];
    __half* As = sh;
    __half* Bs = sh + NSTAGES * A_TILE;

    const int tid  = threadIdx.x;
    const int lane = tid & 31;
    const int wid  = tid >> 5;
    const int g    = lane >> 2;
    const int tg   = lane & 3;
    const int wm   = wid / BNW;
    const int wn   = wid % BNW;

    const int bm = blockIdx.y * BM;
    const int bn = blockIdx.x * BN_;

    const int loff = ((tg ^ (g & 3)) << 3);

    float acc[4][4][4];
#pragma unroll
    for (int i = 0; i < 4; ++i)
#pragma unroll
        for (int j = 0; j < 4; ++j)
#pragma unroll
            for (int k = 0; k < 4; ++k)
                acc[i][j][k] = 0.0f;

    auto issue = [&](int i) {
        const int s = i % NSTAGES;
        const __half* Aseg;
        const __half* Wseg;
        int ld, k0;
        if (i < 32)      { Aseg = x;  Wseg = W0; ld = 1024; k0 = i * BK; }
        else if (i < 64) { Aseg = A1; Wseg = W1; ld = 1024; k0 = (i - 32) * BK; }
        else             { Aseg = c;  Wseg = W2; ld = 2048; k0 = (i - 64) * BK; }

        __half* ad = As + s * A_TILE;
        __half* bd = Bs + s * B_TILE;
#pragma unroll
        for (int j = 0; j < 512 / THREADS; ++j) {
            const int idx = tid + j * THREADS;
            const int row = idx >> 2;
            const int ch  = idx & 3;
            const int swc = ch ^ (row & 3);
            cp16(ad + row * 32 + (swc << 3),
                 Aseg + (size_t)(bm + row) * ld + k0 + (ch << 3));
        }
#pragma unroll
        for (int j = 0; j < (BN_ * 4) / THREADS; ++j) {
            const int idx = tid + j * THREADS;
            const int row = idx >> 2;
            const int ch  = idx & 3;
            const int swc = ch ^ (row & 3);
            cp16(bd + row * 32 + (swc << 3),
                 Wseg + (size_t)(bn + row) * ld + k0 + (ch << 3));
        }
        cp_commit();
    };

    auto consume = [&](int i) {
        const int buf = i % NSTAGES;
        const __half* A0 = As + buf * A_TILE + (wm * 64) * 32;
        const __half* B0 = Bs + buf * B_TILE + (wn * 32) * 32;

        uint4 bv[4];
#pragma unroll
        for (int nf = 0; nf < 4; ++nf)
            bv[nf] = *(const uint4*)(B0 + (nf * 8 + g) * 32 + loff);

#pragma unroll
        for (int mf = 0; mf < 4; ++mf) {
            const uint4 a0 = *(const uint4*)(A0 + (mf * 16 + g) * 32 + loff);
            const uint4 a1 = *(const uint4*)(A0 + (mf * 16 + g + 8) * 32 + loff);
#pragma unroll
            for (int nf = 0; nf < 4; ++nf)
                mma_f16(acc[mf][nf], a0.x, a1.x, a0.y, a1.y, bv[nf].x, bv[nf].y);
#pragma unroll
            for (int nf = 0; nf < 4; ++nf)
                mma_f16(acc[mf][nf], a0.z, a1.z, a0.w, a1.w, bv[nf].z, bv[nf].w);
        }
    };

    // prefill
#pragma unroll
    for (int p = 0; p < PREFILL; ++p) issue(p);

    for (int i = 0; i < NCHUNK; i += BATCH_CH) {
        cp_wait2();           // guarantees chunks i..i+BATCH_CH-1 complete
        __syncthreads();
        // issue into slots consumed during the PREVIOUS iteration
#pragma unroll
        for (int b = 0; b < BATCH_CH; ++b) {
            const int nx = i + PREFILL + b;
            if (nx < NCHUNK) issue(nx);
        }
#pragma unroll
        for (int b = 0; b < BATCH_CH; ++b)
            consume(i + b);
    }

    // ---- epilogue ----
    const bool is_r = (bn < 1024);
    const float* bias = (mode == 2) ? bias_a : (is_r ? bias_a : bias_b - 1024);

#pragma unroll
    for (int mf = 0; mf < 4; ++mf) {
#pragma unroll
        for (int nf = 0; nf < 4; ++nf) {
            const int n = bn + wn * 32 + nf * 8 + 2 * tg;
            const float2 bi = *(const float2*)(bias + n);
#pragma unroll
            for (int half = 0; half < 2; ++half) {
                const int m = bm + wm * 64 + mf * 16 + g + half * 8;
                float v0 = acc[mf][nf][2 * half + 0] + bi.x;
                float v1 = acc[mf][nf][2 * half + 1] + bi.y;
                if (mode == 0) {
                    if (is_r) {
                        const size_t idx = (size_t)m * HID + n;
                        const float2 hp = *(const float2*)(hprev + idx);
                        *(__half2*)(out_h + idx) =
                            __floats2half2_rn(fsigmoid(v0) * hp.x, fsigmoid(v1) * hp.y);
                    } else {
                        const size_t idx = (size_t)m * HID + (n - 1024);
                        float2 o;
                        o.x = fsigmoid(v0);
                        o.y = fsigmoid(v1);
                        *(float2*)(out_f + idx) = o;
                    }
                } else {
                    const size_t idx = (size_t)m * HID + n;
                    const float2 hp = *(const float2*)(hprev + idx);
                    const float2 zz = *(const float2*)(zbuf + idx);
                    float2 o;
                    o.x = fmaf(zz.x, ftanh(v0) - hp.x, hp.x);
                    o.y = fmaf(zz.y, ftanh(v1) - hp.y, hp.y);
                    *(float2*)(out_f + idx) = o;
                }
            }
        }
    }
}

extern "C" void kernel_launch(void* const* d_in, const int* in_sizes, int n_in,
                              void* d_out, int out_size)
{
    const float* x     = (const float*)d_in[0];
    const float* hprev = (const float*)d_in[1];
    const float* c     = (const float*)d_in[2];
    const float* Wh    = (const float*)d_in[3];
    const float* Wz    = (const float*)d_in[4];
    const float* Wr    = (const float*)d_in[5];
    const float* Uh    = (const float*)d_in[6];
    const float* Uz    = (const float*)d_in[7];
    const float* Ur    = (const float*)d_in[8];
    const float* Ch    = (const float*)d_in[9];
    const float* Cz    = (const float*)d_in[10];
    const float* Cr    = (const float*)d_in[11];
    const float* bh    = (const float*)d_in[12];
    const float* bz    = (const float*)d_in[13];
    const float* br    = (const float*)d_in[14];
    float* out = (float*)d_out;

    __half *x2, *h2, *c2, *rh2, *w2;
    float *z_p;
    cudaGetSymbolAddress((void**)&x2,  g_x2);
    cudaGetSymbolAddress((void**)&h2,  g_h2);
    cudaGetSymbolAddress((void**)&c2,  g_c2);
    cudaGetSymbolAddress((void**)&rh2, g_rh2);
    cudaGetSymbolAddress((void**)&z_p, g_z);
    cudaGetSymbolAddress((void**)&w2,  g_w2);

    const size_t M1 = (size_t)1024 * 1024;
    __half* rzW = w2;                 // [2048,1024]
    __half* rzU = w2 + 2 * M1;        // [2048,1024]
    __half* rzC = w2 + 4 * M1;        // [2048,2048]
    __half* hW  = w2 + 8 * M1;        // [1024,1024]
    __half* hU  = w2 + 9 * M1;
    __half* hC  = w2 + 10 * M1;       // [1024,2048]

    // ---- one conversion launch, 12 segments ----
    CvtSegs segs;
    const float* srcs[NSEG] = { x, hprev, c,
                                Wr, Wz, Ur, Uz, Cr, Cz,
                                Wh, Uh, Ch };
    __half* dsts[NSEG] = { x2, h2, c2,
                           rzW, rzW + M1, rzU, rzU + M1, rzC, rzC + 2 * M1,
                           hW, hU, hC };
    const size_t cnts[NSEG] = { (size_t)BATCH * 1024, (size_t)BATCH * 1024, (size_t)BATCH * 2048,
                                M1, M1, M1, M1, 2 * M1, 2 * M1,
                                M1, M1, 2 * M1 };
    int off = 0;
    for (int s = 0; s < NSEG; ++s) {
        segs.src[s] = (const float4*)srcs[s];
        segs.dst[s] = (uint2*)dsts[s];
        segs.off[s] = off;
        off += (int)(cnts[s] / 4);
    }
    segs.off[NSEG] = off;
    cvt_all_kernel<<<2960, 256>>>(segs);

    // rz: BN=128, 256 thr, 2 CTAs/SM, 6 stages, 2 chunks/barrier (prefill 4)
    constexpr int SMEM_RZ = 6 * (A_TILE + 128 * BK) * 2;   // 98304
    // h: BN=64, 128 thr, 4 CTAs/SM, 4 stages, 1 chunk/barrier (prefill 3)
    constexpr int SMEM_H  = 4 * (A_TILE + 64 * BK) * 2;    // 49152

    cudaFuncSetAttribute((const void*)gate_mma_kernel<128, 256, 2, 6, 2>,
                         cudaFuncAttributeMaxDynamicSharedMemorySize, SMEM_RZ);
    cudaFuncSetAttribute((const void*)gate_mma_kernel<64, 128, 4, 4, 1>,
                         cudaFuncAttributeMaxDynamicSharedMemorySize, SMEM_H);

    // fused r+z: N = 2048, grid (16, 64) = 1024 CTAs
    gate_mma_kernel<128, 256, 2, 6, 2><<<dim3(2048 / 128, BATCH / BM), 256, SMEM_RZ>>>(
        x2, h2, c2, rzW, rzU, rzC, br, bz, hprev, nullptr, rh2, z_p, 0);
    // h gate: N = 1024, BN=64 -> grid (16, 64) = 1024 CTAs, 4/SM
    gate_mma_kernel<64, 128, 4, 4, 1><<<dim3(1024 / 64, BATCH / BM), 128, SMEM_H>>>(
        x2, rh2, c2, hW, hU, hC, bh, nullptr, hprev, z_p, nullptr, out, 2);
}